// round 7
// baseline (speedup 1.0000x reference)
#include <cuda_runtime.h>
#include <cuda_bf16.h>
#include <cstdint>
#include <cstddef>

// Problem constants
#define NB 4096   // batch B
#define ND 768    // embedding D
#define NN 8192   // cat rows N
#define NS 4      // sources S

// ---------------- scratch (device globals; no allocations allowed) ----------
__device__ __nv_bfloat16 g_catb[NN * ND];              // 12 MB
__device__ __nv_bfloat16 g_xb[NB * ND];                //  6 MB
__device__ float g_con[(size_t)NN * NB];               // 128 MB
__device__ float g_s4part[32][NB];                     // norm4 partials
__device__ float g_inv_norm[NB];
__device__ float g_zpart[64][NB];                      // softmax denom partials
__device__ float g_wpart[64][NB];                      // y-weighted partials
__device__ float g_theta[NS][NB];

// ---------------- convert fp32 -> bf16 --------------------------------------
__global__ void convert_kernel(const float* __restrict__ cat,
                               const float* __restrict__ x) {
    int i = blockIdx.x * blockDim.x + threadIdx.x;
    const int totCat = NN * ND / 4;
    const int totX   = NB * ND / 4;
    if (i < totCat) {
        float4 v = ((const float4*)cat)[i];
        __nv_bfloat16* p = &g_catb[i * 4];
        p[0] = __float2bfloat16(v.x); p[1] = __float2bfloat16(v.y);
        p[2] = __float2bfloat16(v.z); p[3] = __float2bfloat16(v.w);
    } else if (i < totCat + totX) {
        int j = i - totCat;
        float4 v = ((const float4*)x)[j];
        __nv_bfloat16* p = &g_xb[j * 4];
        p[0] = __float2bfloat16(v.x); p[1] = __float2bfloat16(v.y);
        p[2] = __float2bfloat16(v.z); p[3] = __float2bfloat16(v.w);
    }
}

// ---------------- GEMM: con[N,B] = cat[N,D] @ x[B,D]^T ----------------------
#define BM 128
#define BN 128
#define BKK 32
#define ASTRIDE 40   // bf16 row stride in smem (32 + 8 pad): conflict-free frags

__device__ __forceinline__ void cp16(void* smem, const void* gmem) {
    uint32_t s = (uint32_t)__cvta_generic_to_shared(smem);
    asm volatile("cp.async.cg.shared.global [%0], [%1], 16;\n"
                 :: "r"(s), "l"(gmem));
}

__device__ __forceinline__ void mma16816(float* c, const uint32_t* a, const uint32_t* b) {
    asm volatile(
        "mma.sync.aligned.m16n8k16.row.col.f32.bf16.bf16.f32 "
        "{%0,%1,%2,%3}, {%4,%5,%6,%7}, {%8,%9}, {%0,%1,%2,%3};\n"
        : "+f"(c[0]), "+f"(c[1]), "+f"(c[2]), "+f"(c[3])
        : "r"(a[0]), "r"(a[1]), "r"(a[2]), "r"(a[3]), "r"(b[0]), "r"(b[1]));
}

__device__ __forceinline__ void load_tiles(int kt, __nv_bfloat16* sAb, __nv_bfloat16* sBb,
                                           int bm0, int bn0, int lrow, int lcol) {
    int k0 = kt * BKK;
    #pragma unroll
    for (int i = 0; i < 2; i++) {
        int row = lrow + i * 64;
        cp16(sAb + row * ASTRIDE + lcol, g_catb + (size_t)(bm0 + row) * ND + k0 + lcol);
        cp16(sBb + row * ASTRIDE + lcol, g_xb   + (size_t)(bn0 + row) * ND + k0 + lcol);
    }
    asm volatile("cp.async.commit_group;\n" ::: "memory");
}

__global__ void __launch_bounds__(256, 2) gemm_kernel() {
    __shared__ __nv_bfloat16 sA[2][BM * ASTRIDE];
    __shared__ __nv_bfloat16 sB[2][BN * ASTRIDE];

    const int tid  = threadIdx.x;
    const int lane = tid & 31;
    const int warp = tid >> 5;
    const int wm   = warp & 1;    // 2 warp rows  (64 rows each)
    const int wn   = warp >> 1;   // 4 warp cols  (32 cols each)
    const int bm0  = blockIdx.y * BM;   // n offset
    const int bn0  = blockIdx.x * BN;   // b offset

    const int lrow = tid >> 2;          // 0..63
    const int lcol = (tid & 3) * 8;     // 0,8,16,24

    float acc[4][4][4];
    #pragma unroll
    for (int mt = 0; mt < 4; mt++)
        #pragma unroll
        for (int nt = 0; nt < 4; nt++)
            #pragma unroll
            for (int k = 0; k < 4; k++) acc[mt][nt][k] = 0.f;

    load_tiles(0, sA[0], sB[0], bm0, bn0, lrow, lcol);

    int buf = 0;
    const int NK = ND / BKK;  // 24
    for (int kt = 0; kt < NK; kt++) {
        asm volatile("cp.async.wait_group 0;\n" ::: "memory");
        __syncthreads();
        if (kt + 1 < NK)
            load_tiles(kt + 1, sA[buf ^ 1], sB[buf ^ 1], bm0, bn0, lrow, lcol);

        #pragma unroll
        for (int ks = 0; ks < 2; ks++) {
            const int kk = ks * 16 + (lane & 3) * 2;
            uint32_t af[4][4];
            #pragma unroll
            for (int mt = 0; mt < 4; mt++) {
                const __nv_bfloat16* p =
                    &sA[buf][(wm * 64 + mt * 16 + (lane >> 2)) * ASTRIDE + kk];
                af[mt][0] = *(const uint32_t*)p;
                af[mt][1] = *(const uint32_t*)(p + 8 * ASTRIDE);
                af[mt][2] = *(const uint32_t*)(p + 8);
                af[mt][3] = *(const uint32_t*)(p + 8 * ASTRIDE + 8);
            }
            uint32_t bfr[4][2];
            #pragma unroll
            for (int nt = 0; nt < 4; nt++) {
                const __nv_bfloat16* p =
                    &sB[buf][(wn * 32 + nt * 8 + (lane >> 2)) * ASTRIDE + kk];
                bfr[nt][0] = *(const uint32_t*)p;
                bfr[nt][1] = *(const uint32_t*)(p + 8);
            }
            #pragma unroll
            for (int mt = 0; mt < 4; mt++)
                #pragma unroll
                for (int nt = 0; nt < 4; nt++)
                    mma16816(acc[mt][nt], af[mt], bfr[nt]);
        }
        buf ^= 1;
    }

    // epilogue: write fp32 con
    #pragma unroll
    for (int mt = 0; mt < 4; mt++) {
        #pragma unroll
        for (int nt = 0; nt < 4; nt++) {
            int r  = bm0 + wm * 64 + mt * 16 + (lane >> 2);
            int cc = bn0 + wn * 32 + nt * 8 + (lane & 3) * 2;
            float2 v01 = make_float2(acc[mt][nt][0], acc[mt][nt][1]);
            float2 v23 = make_float2(acc[mt][nt][2], acc[mt][nt][3]);
            *(float2*)&g_con[(size_t)r * NB + cc]       = v01;
            *(float2*)&g_con[(size_t)(r + 8) * NB + cc] = v23;
        }
    }
}

// ---------------- pass A: per-column sum of con^4 (partials) ----------------
__global__ void norm_pass() {
    int b  = blockIdx.x * 256 + threadIdx.x;
    int n0 = blockIdx.y * 256;
    const float* p = g_con + (size_t)n0 * NB + b;
    float acc = 0.f;
    #pragma unroll 8
    for (int i = 0; i < 256; i++) {
        float v  = p[(size_t)i * NB];
        float v2 = v * v;
        acc = fmaf(v2, v2, acc);
    }
    g_s4part[blockIdx.y][b] = acc;
}

__global__ void norm_finalize() {
    int b = blockIdx.x * 256 + threadIdx.x;
    float s = 0.f;
    #pragma unroll
    for (int i = 0; i < 32; i++) s += g_s4part[i][b];
    float nrm = sqrtf(sqrtf(s));            // (sum |con|^4)^(1/4)
    nrm = fmaxf(nrm, 1e-12f);
    g_inv_norm[b] = 1.0f / nrm;
}

// ---------------- theta[s,b] = exp(x[b] . phi[s])  (fp32) -------------------
__global__ void theta_kernel(const float* __restrict__ x, const float* __restrict__ phi) {
    int gw   = (blockIdx.x * blockDim.x + threadIdx.x) >> 5;
    int lane = threadIdx.x & 31;
    int s = gw >> 12;        // / 4096
    int b = gw & (NB - 1);
    const float* xr = x   + (size_t)b * ND;
    const float* pr = phi + (size_t)s * ND;
    float acc = 0.f;
    #pragma unroll
    for (int d = lane; d < ND; d += 32) acc = fmaf(xr[d], pr[d], acc);
    #pragma unroll
    for (int off = 16; off; off >>= 1) acc += __shfl_xor_sync(0xffffffffu, acc, off);
    if (lane == 0) g_theta[s][b] = expf(acc);
}

// ---------------- pass B: per-column exp sums (Z, y-weighted) ---------------
__global__ void exp_pass(const int* __restrict__ y) {
    int b  = blockIdx.x * 256 + threadIdx.x;
    int n0 = blockIdx.y * 128;                 // 128 rows per block, within one source chunk
    float inv = g_inv_norm[b];
    const float* p = g_con + (size_t)n0 * NB + b;
    float z = 0.f, w = 0.f;
    #pragma unroll 4
    for (int i = 0; i < 128; i++) {
        float e = expf(p[(size_t)i * NB] * inv);
        z += e;
        if (__ldg(&y[n0 + i])) w += e;
    }
    g_zpart[blockIdx.y][b] = z;
    g_wpart[blockIdx.y][b] = w;
}

// ---------------- final: sigmoid( sum_s theta*wsum / Z + bias ) -------------
__global__ void final_kernel(const float* __restrict__ bias, float* __restrict__ out) {
    int b = blockIdx.x * 256 + threadIdx.x;
    float Z = 0.f;
    #pragma unroll
    for (int i = 0; i < 64; i++) Z += g_zpart[i][b];
    float sum = 0.f;
    #pragma unroll
    for (int s = 0; s < NS; s++) {
        float w = 0.f;
        #pragma unroll
        for (int i = 0; i < 16; i++) w += g_wpart[s * 16 + i][b];
        sum += w * g_theta[s][b];
    }
    float r = sum / Z + bias[0];
    out[b] = 1.0f / (1.0f + expf(-r));
}

// ---------------- launch -----------------------------------------------------
extern "C" void kernel_launch(void* const* d_in, const int* in_sizes, int n_in,
                              void* d_out, int out_size) {
    // Identify inputs by element count (all distinct) — robust to ordering.
    const float* x = nullptr; const float* cat = nullptr; const float* phi = nullptr;
    const float* bias = nullptr; const int* y = nullptr;
    for (int i = 0; i < n_in; i++) {
        switch (in_sizes[i]) {
            case NB * ND: x    = (const float*)d_in[i]; break;   // 3145728
            case NN * ND: cat  = (const float*)d_in[i]; break;   // 6291456
            case NN:      y    = (const int*)d_in[i];   break;   // 8192
            case NS * ND: phi  = (const float*)d_in[i]; break;   // 3072
            case 1:       bias = (const float*)d_in[i]; break;
            default: break;
        }
    }
    float* out = (float*)d_out;

    const int tot4 = (NN * ND + NB * ND) / 4;
    convert_kernel<<<(tot4 + 255) / 256, 256>>>(cat, x);
    gemm_kernel<<<dim3(NB / BN, NN / BM), 256>>>();
    norm_pass<<<dim3(NB / 256, NN / 256), 256>>>();
    norm_finalize<<<NB / 256, 256>>>();
    theta_kernel<<<(NS * NB * 32) / 256, 256>>>(x, phi);
    exp_pass<<<dim3(NB / 256, NN / 128), 256>>>(y);
    final_kernel<<<NB / 256, 256>>>(bias, out);
}

// round 10
// speedup vs baseline: 1.4591x; 1.4591x over previous
#include <cuda_runtime.h>
#include <cuda_fp16.h>
#include <cuda_bf16.h>
#include <cstdint>
#include <cstddef>

// Problem constants
#define NB 4096   // batch B
#define ND 768    // embedding D
#define NN 8192   // cat rows N
#define NS 4      // sources S

// ---------------- scratch (device globals; no allocations allowed) ----------
__device__ __nv_bfloat16 g_catb[NN * ND];              // 12 MB
__device__ __nv_bfloat16 g_xb[NB * ND];                //  6 MB
__device__ __half g_conh[(size_t)NN * NB];             // 64 MB (fp16 con)
__device__ float g_s4part[32][NB];                     // norm4 partials
__device__ float g_inv_norm[NB];
__device__ float g_zpart[64][NB];                      // softmax denom partials
__device__ float g_wpart[64][NB];                      // y-weighted partials
__device__ float g_theta[NS][NB];

// ---------------- helpers ----------------------------------------------------
__device__ __forceinline__ uint32_t smem_u32(const void* p) {
    uint32_t a;
    asm("{ .reg .u64 t; cvta.to.shared.u64 t, %1; cvt.u32.u64 %0, t; }" : "=r"(a) : "l"(p));
    return a;
}

__device__ __forceinline__ void cp16(uint32_t smem, const void* gmem) {
    asm volatile("cp.async.cg.shared.global [%0], [%1], 16;\n" :: "r"(smem), "l"(gmem));
}

__device__ __forceinline__ void ldsm4(uint32_t* r, uint32_t addr) {
    asm volatile("ldmatrix.sync.aligned.m8n8.x4.shared.b16 {%0,%1,%2,%3}, [%4];"
                 : "=r"(r[0]), "=r"(r[1]), "=r"(r[2]), "=r"(r[3]) : "r"(addr));
}

__device__ __forceinline__ void mma16816(float* c, const uint32_t* a, const uint32_t* b) {
    asm volatile(
        "mma.sync.aligned.m16n8k16.row.col.f32.bf16.bf16.f32 "
        "{%0,%1,%2,%3}, {%4,%5,%6,%7}, {%8,%9}, {%0,%1,%2,%3};\n"
        : "+f"(c[0]), "+f"(c[1]), "+f"(c[2]), "+f"(c[3])
        : "r"(a[0]), "r"(a[1]), "r"(a[2]), "r"(a[3]), "r"(b[0]), "r"(b[1]));
}

// ---------------- convert fp32 -> bf16 --------------------------------------
__global__ void convert_kernel(const float* __restrict__ cat,
                               const float* __restrict__ x) {
    int i = blockIdx.x * blockDim.x + threadIdx.x;
    const int totCat = NN * ND / 4;
    const int totX   = NB * ND / 4;
    if (i < totCat) {
        float4 v = ((const float4*)cat)[i];
        __nv_bfloat16* p = &g_catb[i * 4];
        p[0] = __float2bfloat16(v.x); p[1] = __float2bfloat16(v.y);
        p[2] = __float2bfloat16(v.z); p[3] = __float2bfloat16(v.w);
    } else if (i < totCat + totX) {
        int j = i - totCat;
        float4 v = ((const float4*)x)[j];
        __nv_bfloat16* p = &g_xb[j * 4];
        p[0] = __float2bfloat16(v.x); p[1] = __float2bfloat16(v.y);
        p[2] = __float2bfloat16(v.z); p[3] = __float2bfloat16(v.w);
    }
}

// ---------------- GEMM: con[N,B] = cat[N,D] @ x[B,D]^T ----------------------
// 128x256 CTA tile, 8 warps (2x4) at 64x64 each, K-chunk 32, 3-stage cp.async.
#define BM 128
#define BN 256
#define BKK 32
#define NKC (ND / BKK)          // 24
#define ST 3
#define ASTR 40                 // bf16 row stride (32 + 8 pad), ldmatrix conflict-free
#define A_ELEMS (BM * ASTR)     // 5120
#define B_ELEMS (BN * ASTR)     // 10240
#define B_OFF_BYTES (ST * A_ELEMS * 2)                 // 30720
#define SM_TOTAL (ST * (A_ELEMS + B_ELEMS) * 2)        // 92160

__device__ __forceinline__ void load_chunk(uint32_t sbase, int kt, int s,
                                           int bm0, int bn0, int tid) {
    const int k0 = kt * BKK;
    #pragma unroll
    for (int t = 0; t < 2; t++) {            // A: 128 rows x 4 x 16B
        int idx = tid + t * 256;
        int row = idx >> 2, c = (idx & 3) * 8;
        const void* g = g_catb + (size_t)(bm0 + row) * ND + k0 + c;
        cp16(sbase + (s * A_ELEMS + row * ASTR + c) * 2, g);
    }
    #pragma unroll
    for (int t = 0; t < 4; t++) {            // B: 256 rows x 4 x 16B
        int idx = tid + t * 256;
        int row = idx >> 2, c = (idx & 3) * 8;
        const void* g = g_xb + (size_t)(bn0 + row) * ND + k0 + c;
        cp16(sbase + B_OFF_BYTES + (s * B_ELEMS + row * ASTR + c) * 2, g);
    }
    asm volatile("cp.async.commit_group;\n" ::: "memory");
}

__global__ void __launch_bounds__(256, 1) gemm_kernel() {
    extern __shared__ char smem[];
    const uint32_t sbase = smem_u32(smem);

    const int tid  = threadIdx.x;
    const int lane = tid & 31;
    const int warp = tid >> 5;
    const int wm   = warp & 1;     // 2 warp rows (64 each)
    const int wn   = warp >> 1;    // 4 warp cols (64 each)
    const int bm0  = blockIdx.y * BM;    // n offset
    const int bn0  = blockIdx.x * BN;    // b offset

    // ldmatrix lane addressing (identical pattern for A and B tiles of 16x16)
    const int lr = lane & 15;            // row within 16-tile
    const int lc = (lane >> 4) * 8;      // k sub-offset 0/8

    float acc[4][8][4];
    #pragma unroll
    for (int mt = 0; mt < 4; mt++)
        #pragma unroll
        for (int nt = 0; nt < 8; nt++)
            #pragma unroll
            for (int k = 0; k < 4; k++) acc[mt][nt][k] = 0.f;

    load_chunk(sbase, 0, 0, bm0, bn0, tid);
    load_chunk(sbase, 1, 1, bm0, bn0, tid);

    for (int kt = 0; kt < NKC; kt++) {
        const int s = kt % ST;
        if (kt < NKC - 1) asm volatile("cp.async.wait_group 1;\n" ::: "memory");
        else              asm volatile("cp.async.wait_group 0;\n" ::: "memory");
        __syncthreads();   // all warps done with stage being overwritten next

        if (kt + 2 < NKC)
            load_chunk(sbase, kt + 2, (kt + 2) % ST, bm0, bn0, tid);

        #pragma unroll
        for (int ks = 0; ks < 2; ks++) {
            uint32_t af[4][4], bb[4][4];
            const uint32_t abase =
                sbase + (s * A_ELEMS + (wm * 64 + lr) * ASTR + ks * 16 + lc) * 2;
            #pragma unroll
            for (int mt = 0; mt < 4; mt++)
                ldsm4(af[mt], abase + mt * 16 * ASTR * 2);
            const uint32_t bbase =
                sbase + B_OFF_BYTES + (s * B_ELEMS + (wn * 64 + lr) * ASTR + ks * 16 + lc) * 2;
            #pragma unroll
            for (int p = 0; p < 4; p++)
                ldsm4(bb[p], bbase + p * 16 * ASTR * 2);

            #pragma unroll
            for (int mt = 0; mt < 4; mt++)
                #pragma unroll
                for (int nt = 0; nt < 8; nt++) {
                    uint32_t bfr[2] = { bb[nt >> 1][nt & 1], bb[nt >> 1][2 + (nt & 1)] };
                    mma16816(acc[mt][nt], af[mt], bfr);
                }
        }
    }

    // epilogue: fp16 con
    #pragma unroll
    for (int mt = 0; mt < 4; mt++) {
        #pragma unroll
        for (int nt = 0; nt < 8; nt++) {
            const int r = bm0 + wm * 64 + mt * 16 + (lane >> 2);
            const int c = bn0 + wn * 64 + nt * 8 + (lane & 3) * 2;
            __half2 h01 = __floats2half2_rn(acc[mt][nt][0], acc[mt][nt][1]);
            __half2 h23 = __floats2half2_rn(acc[mt][nt][2], acc[mt][nt][3]);
            *(__half2*)&g_conh[(size_t)r * NB + c]       = h01;
            *(__half2*)&g_conh[(size_t)(r + 8) * NB + c] = h23;
        }
    }
}

// ---------------- pass A: per-column sum of con^4 (partials) ----------------
__global__ void norm_pass() {
    int b  = blockIdx.x * 256 + threadIdx.x;
    int n0 = blockIdx.y * 256;
    const __half* p = g_conh + (size_t)n0 * NB + b;
    float acc = 0.f;
    #pragma unroll 8
    for (int i = 0; i < 256; i++) {
        float v  = __half2float(p[(size_t)i * NB]);
        float v2 = v * v;
        acc = fmaf(v2, v2, acc);
    }
    g_s4part[blockIdx.y][b] = acc;
}

__global__ void norm_finalize() {
    int b = blockIdx.x * 256 + threadIdx.x;
    float s = 0.f;
    #pragma unroll
    for (int i = 0; i < 32; i++) s += g_s4part[i][b];
    float nrm = sqrtf(sqrtf(s));
    nrm = fmaxf(nrm, 1e-12f);
    g_inv_norm[b] = 1.0f / nrm;
}

// ---------------- theta[s,b] = exp(x[b] . phi[s])  (fp32) -------------------
__global__ void theta_kernel(const float* __restrict__ x, const float* __restrict__ phi) {
    int gw   = (blockIdx.x * blockDim.x + threadIdx.x) >> 5;
    int lane = threadIdx.x & 31;
    int s = gw >> 12;
    int b = gw & (NB - 1);
    const float* xr = x   + (size_t)b * ND;
    const float* pr = phi + (size_t)s * ND;
    float acc = 0.f;
    #pragma unroll
    for (int d = lane; d < ND; d += 32) acc = fmaf(xr[d], pr[d], acc);
    #pragma unroll
    for (int off = 16; off; off >>= 1) acc += __shfl_xor_sync(0xffffffffu, acc, off);
    if (lane == 0) g_theta[s][b] = expf(acc);
}

// ---------------- pass B: per-column exp sums (Z, y-weighted) ---------------
__global__ void exp_pass(const int* __restrict__ y) {
    int b  = blockIdx.x * 256 + threadIdx.x;
    int n0 = blockIdx.y * 128;
    float inv = g_inv_norm[b];
    const __half* p = g_conh + (size_t)n0 * NB + b;
    float z = 0.f, w = 0.f;
    #pragma unroll 4
    for (int i = 0; i < 128; i++) {
        float e = expf(__half2float(p[(size_t)i * NB]) * inv);
        z += e;
        if (__ldg(&y[n0 + i])) w += e;
    }
    g_zpart[blockIdx.y][b] = z;
    g_wpart[blockIdx.y][b] = w;
}

// ---------------- final: sigmoid( sum_s theta*wsum / Z + bias ) -------------
__global__ void final_kernel(const float* __restrict__ bias, float* __restrict__ out) {
    int b = blockIdx.x * 256 + threadIdx.x;
    float Z = 0.f;
    #pragma unroll
    for (int i = 0; i < 64; i++) Z += g_zpart[i][b];
    float sum = 0.f;
    #pragma unroll
    for (int s = 0; s < NS; s++) {
        float w = 0.f;
        #pragma unroll
        for (int i = 0; i < 16; i++) w += g_wpart[s * 16 + i][b];
        sum += w * g_theta[s][b];
    }
    float r = sum / Z + bias[0];
    out[b] = 1.0f / (1.0f + expf(-r));
}

// ---------------- launch -----------------------------------------------------
extern "C" void kernel_launch(void* const* d_in, const int* in_sizes, int n_in,
                              void* d_out, int out_size) {
    const float* x = nullptr; const float* cat = nullptr; const float* phi = nullptr;
    const float* bias = nullptr; const int* y = nullptr;
    for (int i = 0; i < n_in; i++) {
        switch (in_sizes[i]) {
            case NB * ND: x    = (const float*)d_in[i]; break;
            case NN * ND: cat  = (const float*)d_in[i]; break;
            case NN:      y    = (const int*)d_in[i];   break;
            case NS * ND: phi  = (const float*)d_in[i]; break;
            case 1:       bias = (const float*)d_in[i]; break;
            default: break;
        }
    }
    float* out = (float*)d_out;

    cudaFuncSetAttribute(gemm_kernel, cudaFuncAttributeMaxDynamicSharedMemorySize, SM_TOTAL);

    const int tot4 = (NN * ND + NB * ND) / 4;
    convert_kernel<<<(tot4 + 255) / 256, 256>>>(cat, x);
    gemm_kernel<<<dim3(NB / BN, NN / BM), 256, SM_TOTAL>>>();
    norm_pass<<<dim3(NB / 256, NN / 256), 256>>>();
    norm_finalize<<<NB / 256, 256>>>();
    theta_kernel<<<(NS * NB * 32) / 256, 256>>>(x, phi);
    exp_pass<<<dim3(NB / 256, NN / 128), 256>>>(y);
    final_kernel<<<NB / 256, 256>>>(bias, out);
}

// round 11
// speedup vs baseline: 1.5747x; 1.0792x over previous
#include <cuda_runtime.h>
#include <cuda_fp16.h>
#include <cuda_bf16.h>
#include <cstdint>
#include <cstddef>

// Problem constants
#define NB 4096   // batch B
#define ND 768    // embedding D
#define NN 8192   // cat rows N
#define NS 4      // sources S

// ---------------- scratch (device globals; no allocations allowed) ----------
__device__ __nv_bfloat16 g_catb[NN * ND];              // 12 MB
__device__ __nv_bfloat16 g_xb[NB * ND];                //  6 MB
__device__ __half g_conh[(size_t)NN * NB];             // 64 MB (fp16 con)
__device__ float g_s4part[128][NB];                    // norm4 partials (2 per N-tile)
__device__ float g_inv_norm[NB];
__device__ float g_zpart[64][NB];                      // softmax denom partials
__device__ float g_wpart[64][NB];                      // y-weighted partials
__device__ float g_theta[NS][NB];

// ---------------- helpers ----------------------------------------------------
__device__ __forceinline__ uint32_t smem_u32(const void* p) {
    uint32_t a;
    asm("{ .reg .u64 t; cvta.to.shared.u64 t, %1; cvt.u32.u64 %0, t; }" : "=r"(a) : "l"(p));
    return a;
}

__device__ __forceinline__ void cp16(uint32_t smem, const void* gmem) {
    asm volatile("cp.async.cg.shared.global [%0], [%1], 16;\n" :: "r"(smem), "l"(gmem));
}

__device__ __forceinline__ void ldsm4(uint32_t* r, uint32_t addr) {
    asm volatile("ldmatrix.sync.aligned.m8n8.x4.shared.b16 {%0,%1,%2,%3}, [%4];"
                 : "=r"(r[0]), "=r"(r[1]), "=r"(r[2]), "=r"(r[3]) : "r"(addr));
}

__device__ __forceinline__ void mma16816(float* c, const uint32_t* a, const uint32_t* b) {
    asm volatile(
        "mma.sync.aligned.m16n8k16.row.col.f32.bf16.bf16.f32 "
        "{%0,%1,%2,%3}, {%4,%5,%6,%7}, {%8,%9}, {%0,%1,%2,%3};\n"
        : "+f"(c[0]), "+f"(c[1]), "+f"(c[2]), "+f"(c[3])
        : "r"(a[0]), "r"(a[1]), "r"(a[2]), "r"(a[3]), "r"(b[0]), "r"(b[1]));
}

// ---------------- convert fp32 -> bf16 --------------------------------------
__global__ void convert_kernel(const float* __restrict__ cat,
                               const float* __restrict__ x) {
    int i = blockIdx.x * blockDim.x + threadIdx.x;
    const int totCat = NN * ND / 4;
    const int totX   = NB * ND / 4;
    if (i < totCat) {
        float4 v = ((const float4*)cat)[i];
        __nv_bfloat16* p = &g_catb[i * 4];
        p[0] = __float2bfloat16(v.x); p[1] = __float2bfloat16(v.y);
        p[2] = __float2bfloat16(v.z); p[3] = __float2bfloat16(v.w);
    } else if (i < totCat + totX) {
        int j = i - totCat;
        float4 v = ((const float4*)x)[j];
        __nv_bfloat16* p = &g_xb[j * 4];
        p[0] = __float2bfloat16(v.x); p[1] = __float2bfloat16(v.y);
        p[2] = __float2bfloat16(v.z); p[3] = __float2bfloat16(v.w);
    }
}

// ---------------- GEMM: con[N,B] = cat[N,D] @ x[B,D]^T ----------------------
// 128x256 CTA tile, 8 warps (2x4) at 64x64 each, K-chunk 32, 4-stage cp.async.
#define BM 128
#define BN 256
#define BKK 32
#define NKC (ND / BKK)          // 24
#define ST 4
#define ASTR 40                 // bf16 row stride (32 + 8 pad), ldmatrix conflict-free
#define A_ELEMS (BM * ASTR)     // 5120
#define B_ELEMS (BN * ASTR)     // 10240
#define B_OFF_BYTES (ST * A_ELEMS * 2)                 // 40960
#define SM_TOTAL (ST * (A_ELEMS + B_ELEMS) * 2)        // 122880
#define CSTR 264                // epilogue staging stride (halves)

__device__ __forceinline__ void load_chunk(uint32_t sbase, int kt, int s,
                                           int bm0, int bn0, int tid) {
    const int k0 = kt * BKK;
    #pragma unroll
    for (int t = 0; t < 2; t++) {            // A: 128 rows x 4 x 16B
        int idx = tid + t * 256;
        int row = idx >> 2, c = (idx & 3) * 8;
        const void* g = g_catb + (size_t)(bm0 + row) * ND + k0 + c;
        cp16(sbase + (s * A_ELEMS + row * ASTR + c) * 2, g);
    }
    #pragma unroll
    for (int t = 0; t < 4; t++) {            // B: 256 rows x 4 x 16B
        int idx = tid + t * 256;
        int row = idx >> 2, c = (idx & 3) * 8;
        const void* g = g_xb + (size_t)(bn0 + row) * ND + k0 + c;
        cp16(sbase + B_OFF_BYTES + (s * B_ELEMS + row * ASTR + c) * 2, g);
    }
    asm volatile("cp.async.commit_group;\n" ::: "memory");
}

__global__ void __launch_bounds__(256, 1) gemm_kernel() {
    extern __shared__ char smem[];
    const uint32_t sbase = smem_u32(smem);

    const int tid  = threadIdx.x;
    const int lane = tid & 31;
    const int warp = tid >> 5;
    const int wm   = warp & 1;     // 2 warp rows (64 each)
    const int wn   = warp >> 1;    // 4 warp cols (64 each)
    const int bm0  = blockIdx.y * BM;    // n offset
    const int bn0  = blockIdx.x * BN;    // b offset

    const int lr = lane & 15;            // ldmatrix row within 16-tile
    const int lc = (lane >> 4) * 8;      // k sub-offset 0/8

    float acc[4][8][4];
    #pragma unroll
    for (int mt = 0; mt < 4; mt++)
        #pragma unroll
        for (int nt = 0; nt < 8; nt++)
            #pragma unroll
            for (int k = 0; k < 4; k++) acc[mt][nt][k] = 0.f;

    load_chunk(sbase, 0, 0, bm0, bn0, tid);
    load_chunk(sbase, 1, 1, bm0, bn0, tid);
    load_chunk(sbase, 2, 2, bm0, bn0, tid);

    for (int kt = 0; kt < NKC; kt++) {
        const int s = kt & 3;
        if (kt < NKC - 2)       asm volatile("cp.async.wait_group 2;\n" ::: "memory");
        else if (kt == NKC - 2) asm volatile("cp.async.wait_group 1;\n" ::: "memory");
        else                    asm volatile("cp.async.wait_group 0;\n" ::: "memory");
        __syncthreads();

        if (kt + 3 < NKC)
            load_chunk(sbase, kt + 3, (kt + 3) & 3, bm0, bn0, tid);

        #pragma unroll
        for (int ks = 0; ks < 2; ks++) {
            uint32_t af[4][4], bb[4][4];
            const uint32_t abase =
                sbase + (s * A_ELEMS + (wm * 64 + lr) * ASTR + ks * 16 + lc) * 2;
            #pragma unroll
            for (int mt = 0; mt < 4; mt++)
                ldsm4(af[mt], abase + mt * 16 * ASTR * 2);
            const uint32_t bbase =
                sbase + B_OFF_BYTES + (s * B_ELEMS + (wn * 64 + lr) * ASTR + ks * 16 + lc) * 2;
            #pragma unroll
            for (int p = 0; p < 4; p++)
                ldsm4(bb[p], bbase + p * 16 * ASTR * 2);

            #pragma unroll
            for (int mt = 0; mt < 4; mt++)
                #pragma unroll
                for (int nt = 0; nt < 8; nt++) {
                    uint32_t bfr[2] = { bb[nt >> 1][nt & 1], bb[nt >> 1][2 + (nt & 1)] };
                    mma16816(acc[mt][nt], af[mt], bfr);
                }
        }
    }

    // ---- fused per-column sum(v^4) over this warp's 64 rows ----
    // thread holds cols c0=(lane&3)*2, c0+1; rows (lane>>2)+mt*16+{0,8}.
    #pragma unroll
    for (int nt = 0; nt < 8; nt++) {
        float se = 0.f, so = 0.f;
        #pragma unroll
        for (int mt = 0; mt < 4; mt++) {
            float a0 = acc[mt][nt][0], a1 = acc[mt][nt][1];
            float a2 = acc[mt][nt][2], a3 = acc[mt][nt][3];
            se = fmaf(a0 * a0, a0 * a0, se); se = fmaf(a2 * a2, a2 * a2, se);
            so = fmaf(a1 * a1, a1 * a1, so); so = fmaf(a3 * a3, a3 * a3, so);
        }
        #pragma unroll
        for (int m = 4; m <= 16; m <<= 1) {   // reduce over lane>>2 (same lane&3)
            se += __shfl_xor_sync(0xffffffffu, se, m);
            so += __shfl_xor_sync(0xffffffffu, so, m);
        }
        if (lane < 4) {
            int c = bn0 + wn * 64 + nt * 8 + lane * 2;
            int slot = blockIdx.y * 2 + wm;
            g_s4part[slot][c]     = se;
            g_s4part[slot][c + 1] = so;
        }
    }

    // ---- epilogue: stage fp16 tile in smem, write coalesced rows ----
    __syncthreads();                       // smem ring no longer needed
    __half* sst = (__half*)smem;
    #pragma unroll
    for (int mt = 0; mt < 4; mt++) {
        #pragma unroll
        for (int nt = 0; nt < 8; nt++) {
            const int r = wm * 64 + mt * 16 + (lane >> 2);
            const int c = wn * 64 + nt * 8 + (lane & 3) * 2;
            *(__half2*)&sst[r * CSTR + c] =
                __floats2half2_rn(acc[mt][nt][0], acc[mt][nt][1]);
            *(__half2*)&sst[(r + 8) * CSTR + c] =
                __floats2half2_rn(acc[mt][nt][2], acc[mt][nt][3]);
        }
    }
    __syncthreads();
    #pragma unroll
    for (int i = 0; i < 16; i++) {
        const int r = warp * 16 + i;
        uint4 v = *(const uint4*)&sst[r * CSTR + lane * 8];
        *(uint4*)&g_conh[(size_t)(bm0 + r) * NB + bn0 + lane * 8] = v;
    }
}

// ---------------- norm finalize: inv 4-norm per column ----------------------
__global__ void norm_finalize() {
    int b = blockIdx.x * 256 + threadIdx.x;
    float s = 0.f;
    #pragma unroll
    for (int i = 0; i < 128; i++) s += g_s4part[i][b];
    float nrm = sqrtf(sqrtf(s));
    nrm = fmaxf(nrm, 1e-12f);
    g_inv_norm[b] = 1.0f / nrm;
}

// ---------------- theta[s,b] = exp(x[b] . phi[s])  (fp32) -------------------
__global__ void theta_kernel(const float* __restrict__ x, const float* __restrict__ phi) {
    int gw   = (blockIdx.x * blockDim.x + threadIdx.x) >> 5;
    int lane = threadIdx.x & 31;
    int s = gw >> 12;
    int b = gw & (NB - 1);
    const float* xr = x   + (size_t)b * ND;
    const float* pr = phi + (size_t)s * ND;
    float acc = 0.f;
    #pragma unroll
    for (int d = lane; d < ND; d += 32) acc = fmaf(xr[d], pr[d], acc);
    #pragma unroll
    for (int off = 16; off; off >>= 1) acc += __shfl_xor_sync(0xffffffffu, acc, off);
    if (lane == 0) g_theta[s][b] = expf(acc);
}

// ---------------- pass B: per-column exp sums (Z, y-weighted) ---------------
__global__ void exp_pass(const int* __restrict__ y) {
    int b  = blockIdx.x * 256 + threadIdx.x;
    int n0 = blockIdx.y * 128;
    float inv = g_inv_norm[b];
    const __half* p = g_conh + (size_t)n0 * NB + b;
    float z = 0.f, w = 0.f;
    #pragma unroll 4
    for (int i = 0; i < 128; i++) {
        float e = expf(__half2float(p[(size_t)i * NB]) * inv);
        z += e;
        if (__ldg(&y[n0 + i])) w += e;
    }
    g_zpart[blockIdx.y][b] = z;
    g_wpart[blockIdx.y][b] = w;
}

// ---------------- final: sigmoid( sum_s theta*wsum / Z + bias ) -------------
__global__ void final_kernel(const float* __restrict__ bias, float* __restrict__ out) {
    int b = blockIdx.x * 256 + threadIdx.x;
    float Z = 0.f;
    #pragma unroll
    for (int i = 0; i < 64; i++) Z += g_zpart[i][b];
    float sum = 0.f;
    #pragma unroll
    for (int s = 0; s < NS; s++) {
        float w = 0.f;
        #pragma unroll
        for (int i = 0; i < 16; i++) w += g_wpart[s * 16 + i][b];
        sum += w * g_theta[s][b];
    }
    float r = sum / Z + bias[0];
    out[b] = 1.0f / (1.0f + expf(-r));
}

// ---------------- launch -----------------------------------------------------
extern "C" void kernel_launch(void* const* d_in, const int* in_sizes, int n_in,
                              void* d_out, int out_size) {
    const float* x = nullptr; const float* cat = nullptr; const float* phi = nullptr;
    const float* bias = nullptr; const int* y = nullptr;
    for (int i = 0; i < n_in; i++) {
        switch (in_sizes[i]) {
            case NB * ND: x    = (const float*)d_in[i]; break;
            case NN * ND: cat  = (const float*)d_in[i]; break;
            case NN:      y    = (const int*)d_in[i];   break;
            case NS * ND: phi  = (const float*)d_in[i]; break;
            case 1:       bias = (const float*)d_in[i]; break;
            default: break;
        }
    }
    float* out = (float*)d_out;

    cudaFuncSetAttribute(gemm_kernel, cudaFuncAttributeMaxDynamicSharedMemorySize, SM_TOTAL);

    const int tot4 = (NN * ND + NB * ND) / 4;
    convert_kernel<<<(tot4 + 255) / 256, 256>>>(cat, x);
    gemm_kernel<<<dim3(NB / BN, NN / BM), 256, SM_TOTAL>>>();
    norm_finalize<<<NB / 256, 256>>>();
    theta_kernel<<<(NS * NB * 32) / 256, 256>>>(x, phi);
    exp_pass<<<dim3(NB / 256, NN / 128), 256>>>(y);
    final_kernel<<<NB / 256, 256>>>(bias, out);
}

// round 12
// speedup vs baseline: 1.6133x; 1.0246x over previous
#include <cuda_runtime.h>
#include <cuda_fp16.h>
#include <cuda_bf16.h>
#include <cstdint>
#include <cstddef>

// Problem constants
#define NB 4096   // batch B
#define ND 768    // embedding D
#define NN 8192   // cat rows N
#define NS 4      // sources S

// ---------------- scratch (device globals; no allocations allowed) ----------
__device__ __nv_bfloat16 g_catb[NN * ND];              // 12 MB
__device__ __nv_bfloat16 g_xb[NB * ND];                //  6 MB
__device__ __half g_conh[(size_t)NN * NB];             // 64 MB (fp16 con)
__device__ float g_s4part[128][NB];                    // norm4 partials (2 per N-tile row)
__device__ float g_inv_norm[NB];
__device__ float g_zpart[64][NB];                      // softmax denom partials
__device__ float g_wpart[64][NB];                      // y-weighted partials
__device__ float g_theta[NS][NB];

// ---------------- helpers ----------------------------------------------------
__device__ __forceinline__ uint32_t smem_u32(const void* p) {
    uint32_t a;
    asm("{ .reg .u64 t; cvta.to.shared.u64 t, %1; cvt.u32.u64 %0, t; }" : "=r"(a) : "l"(p));
    return a;
}

__device__ __forceinline__ void cp16(uint32_t smem, const void* gmem) {
    asm volatile("cp.async.cg.shared.global [%0], [%1], 16;\n" :: "r"(smem), "l"(gmem));
}

__device__ __forceinline__ void ldsm4(uint32_t* r, uint32_t addr) {
    asm volatile("ldmatrix.sync.aligned.m8n8.x4.shared.b16 {%0,%1,%2,%3}, [%4];"
                 : "=r"(r[0]), "=r"(r[1]), "=r"(r[2]), "=r"(r[3]) : "r"(addr));
}

__device__ __forceinline__ void mma16816(float* c, const uint32_t* a, const uint32_t* b) {
    asm volatile(
        "mma.sync.aligned.m16n8k16.row.col.f32.bf16.bf16.f32 "
        "{%0,%1,%2,%3}, {%4,%5,%6,%7}, {%8,%9}, {%0,%1,%2,%3};\n"
        : "+f"(c[0]), "+f"(c[1]), "+f"(c[2]), "+f"(c[3])
        : "r"(a[0]), "r"(a[1]), "r"(a[2]), "r"(a[3]), "r"(b[0]), "r"(b[1]));
}

// ---------------- convert fp32 -> bf16 --------------------------------------
__global__ void convert_kernel(const float* __restrict__ cat,
                               const float* __restrict__ x) {
    int i = blockIdx.x * blockDim.x + threadIdx.x;
    const int totCat = NN * ND / 4;
    const int totX   = NB * ND / 4;
    if (i < totCat) {
        float4 v = ((const float4*)cat)[i];
        __nv_bfloat16* p = &g_catb[i * 4];
        p[0] = __float2bfloat16(v.x); p[1] = __float2bfloat16(v.y);
        p[2] = __float2bfloat16(v.z); p[3] = __float2bfloat16(v.w);
    } else if (i < totCat + totX) {
        int j = i - totCat;
        float4 v = ((const float4*)x)[j];
        __nv_bfloat16* p = &g_xb[j * 4];
        p[0] = __float2bfloat16(v.x); p[1] = __float2bfloat16(v.y);
        p[2] = __float2bfloat16(v.z); p[3] = __float2bfloat16(v.w);
    }
}

// ---------------- GEMM: con[N,B] = cat[N,D] @ x[B,D]^T ----------------------
// 128x128 CTA tile, 8 warps (2x4) at 64x32 each, K-chunk 32, 3-stage cp.async,
// 2 CTAs/SM.
#define BM 128
#define BN 128
#define BKK 32
#define NKC (ND / BKK)          // 24
#define ST 3
#define ASTR 40                 // bf16 row stride (32 + 8 pad), ldmatrix conflict-free
#define A_ELEMS (BM * ASTR)     // 5120
#define B_ELEMS (BN * ASTR)     // 5120
#define B_OFF_BYTES (ST * A_ELEMS * 2)                 // 30720
#define SM_TOTAL (ST * (A_ELEMS + B_ELEMS) * 2)        // 61440
#define CSTR 136                // epilogue staging stride (halves)

__device__ __forceinline__ void load_chunk(uint32_t sbase, int kt, int s,
                                           int bm0, int bn0, int tid) {
    const int k0 = kt * BKK;
    #pragma unroll
    for (int t = 0; t < 2; t++) {            // A: 128 rows x 4 x 16B
        int idx = tid + t * 256;
        int row = idx >> 2, c = (idx & 3) * 8;
        const void* g = g_catb + (size_t)(bm0 + row) * ND + k0 + c;
        cp16(sbase + (s * A_ELEMS + row * ASTR + c) * 2, g);
    }
    #pragma unroll
    for (int t = 0; t < 2; t++) {            // B: 128 rows x 4 x 16B
        int idx = tid + t * 256;
        int row = idx >> 2, c = (idx & 3) * 8;
        const void* g = g_xb + (size_t)(bn0 + row) * ND + k0 + c;
        cp16(sbase + B_OFF_BYTES + (s * B_ELEMS + row * ASTR + c) * 2, g);
    }
    asm volatile("cp.async.commit_group;\n" ::: "memory");
}

__global__ void __launch_bounds__(256, 2) gemm_kernel() {
    extern __shared__ char smem[];
    const uint32_t sbase = smem_u32(smem);

    const int tid  = threadIdx.x;
    const int lane = tid & 31;
    const int warp = tid >> 5;
    const int wm   = warp & 1;     // 2 warp rows (64 each)
    const int wn   = warp >> 1;    // 4 warp cols (32 each)
    const int bm0  = blockIdx.y * BM;    // n offset
    const int bn0  = blockIdx.x * BN;    // b offset

    const int lr = lane & 15;            // ldmatrix row within 16-tile
    const int lc = (lane >> 4) * 8;      // k sub-offset 0/8

    float acc[4][4][4];
    #pragma unroll
    for (int mt = 0; mt < 4; mt++)
        #pragma unroll
        for (int nt = 0; nt < 4; nt++)
            #pragma unroll
            for (int k = 0; k < 4; k++) acc[mt][nt][k] = 0.f;

    load_chunk(sbase, 0, 0, bm0, bn0, tid);
    load_chunk(sbase, 1, 1, bm0, bn0, tid);

    for (int kt = 0; kt < NKC; kt++) {
        const int s = kt % ST;
        if (kt < NKC - 1) asm volatile("cp.async.wait_group 1;\n" ::: "memory");
        else              asm volatile("cp.async.wait_group 0;\n" ::: "memory");
        __syncthreads();

        if (kt + 2 < NKC)
            load_chunk(sbase, kt + 2, (kt + 2) % ST, bm0, bn0, tid);

        #pragma unroll
        for (int ks = 0; ks < 2; ks++) {
            uint32_t af[4][4], bb[2][4];
            const uint32_t abase =
                sbase + (s * A_ELEMS + (wm * 64 + lr) * ASTR + ks * 16 + lc) * 2;
            #pragma unroll
            for (int mt = 0; mt < 4; mt++)
                ldsm4(af[mt], abase + mt * 16 * ASTR * 2);
            const uint32_t bbase =
                sbase + B_OFF_BYTES + (s * B_ELEMS + (wn * 32 + lr) * ASTR + ks * 16 + lc) * 2;
            #pragma unroll
            for (int p = 0; p < 2; p++)
                ldsm4(bb[p], bbase + p * 16 * ASTR * 2);

            #pragma unroll
            for (int mt = 0; mt < 4; mt++)
                #pragma unroll
                for (int nt = 0; nt < 4; nt++) {
                    uint32_t bfr[2] = { bb[nt >> 1][nt & 1], bb[nt >> 1][2 + (nt & 1)] };
                    mma16816(acc[mt][nt], af[mt], bfr);
                }
        }
    }

    // ---- fused per-column sum(v^4) over this warp's 64 rows ----
    #pragma unroll
    for (int nt = 0; nt < 4; nt++) {
        float se = 0.f, so = 0.f;
        #pragma unroll
        for (int mt = 0; mt < 4; mt++) {
            float a0 = acc[mt][nt][0], a1 = acc[mt][nt][1];
            float a2 = acc[mt][nt][2], a3 = acc[mt][nt][3];
            se = fmaf(a0 * a0, a0 * a0, se); se = fmaf(a2 * a2, a2 * a2, se);
            so = fmaf(a1 * a1, a1 * a1, so); so = fmaf(a3 * a3, a3 * a3, so);
        }
        #pragma unroll
        for (int m = 4; m <= 16; m <<= 1) {   // reduce over lane>>2 (same lane&3)
            se += __shfl_xor_sync(0xffffffffu, se, m);
            so += __shfl_xor_sync(0xffffffffu, so, m);
        }
        if (lane < 4) {
            int c = bn0 + wn * 32 + nt * 8 + lane * 2;
            int slot = blockIdx.y * 2 + wm;
            g_s4part[slot][c]     = se;
            g_s4part[slot][c + 1] = so;
        }
    }

    // ---- epilogue: stage fp16 tile in smem, write coalesced rows ----
    __syncthreads();                       // smem ring no longer needed
    __half* sst = (__half*)smem;
    #pragma unroll
    for (int mt = 0; mt < 4; mt++) {
        #pragma unroll
        for (int nt = 0; nt < 4; nt++) {
            const int r = wm * 64 + mt * 16 + (lane >> 2);
            const int c = wn * 32 + nt * 8 + (lane & 3) * 2;
            *(__half2*)&sst[r * CSTR + c] =
                __floats2half2_rn(acc[mt][nt][0], acc[mt][nt][1]);
            *(__half2*)&sst[(r + 8) * CSTR + c] =
                __floats2half2_rn(acc[mt][nt][2], acc[mt][nt][3]);
        }
    }
    __syncthreads();
    #pragma unroll
    for (int i = 0; i < 16; i++) {
        const int r = warp * 16 + i;
        uint2 v = *(const uint2*)&sst[r * CSTR + lane * 4];
        *(uint2*)&g_conh[(size_t)(bm0 + r) * NB + bn0 + lane * 4] = v;
    }
}

// ---------------- theta + norm finalize (fused launch) ----------------------
// blocks [0,512): one warp per batch column b, all 4 sources from one x read.
// blocks [512,528): inv 4-norm finalize.
__global__ void theta_norm_kernel(const float* __restrict__ x,
                                  const float* __restrict__ phi) {
    if (blockIdx.x >= 512) {
        int b = (blockIdx.x - 512) * 256 + threadIdx.x;
        float s = 0.f;
        #pragma unroll
        for (int i = 0; i < 128; i++) s += g_s4part[i][b];
        float nrm = sqrtf(sqrtf(s));
        nrm = fmaxf(nrm, 1e-12f);
        g_inv_norm[b] = 1.0f / nrm;
        return;
    }
    const int warp = threadIdx.x >> 5;
    const int lane = threadIdx.x & 31;
    const int b = blockIdx.x * 8 + warp;
    const float* xr = x + (size_t)b * ND;
    float xv[24];
    #pragma unroll
    for (int i = 0; i < 24; i++) xv[i] = xr[lane + i * 32];
    #pragma unroll
    for (int s = 0; s < NS; s++) {
        const float* pr = phi + (size_t)s * ND;
        float acc = 0.f;
        #pragma unroll
        for (int i = 0; i < 24; i++) acc = fmaf(xv[i], pr[lane + i * 32], acc);
        #pragma unroll
        for (int off = 16; off; off >>= 1) acc += __shfl_xor_sync(0xffffffffu, acc, off);
        if (lane == 0) g_theta[s][b] = expf(acc);
    }
}

// ---------------- pass B: per-column exp sums (Z, y-weighted) ---------------
__global__ void exp_pass(const int* __restrict__ y) {
    int b  = blockIdx.x * 256 + threadIdx.x;
    int n0 = blockIdx.y * 128;
    float inv = g_inv_norm[b];
    const __half* p = g_conh + (size_t)n0 * NB + b;
    float z = 0.f, w = 0.f;
    #pragma unroll 4
    for (int i = 0; i < 128; i++) {
        float e = expf(__half2float(p[(size_t)i * NB]) * inv);
        z += e;
        if (__ldg(&y[n0 + i])) w += e;
    }
    g_zpart[blockIdx.y][b] = z;
    g_wpart[blockIdx.y][b] = w;
}

// ---------------- final: sigmoid( sum_s theta*wsum / Z + bias ) -------------
__global__ void final_kernel(const float* __restrict__ bias, float* __restrict__ out) {
    int b = blockIdx.x * 256 + threadIdx.x;
    float Z = 0.f;
    #pragma unroll
    for (int i = 0; i < 64; i++) Z += g_zpart[i][b];
    float sum = 0.f;
    #pragma unroll
    for (int s = 0; s < NS; s++) {
        float w = 0.f;
        #pragma unroll
        for (int i = 0; i < 16; i++) w += g_wpart[s * 16 + i][b];
        sum += w * g_theta[s][b];
    }
    float r = sum / Z + bias[0];
    out[b] = 1.0f / (1.0f + expf(-r));
}

// ---------------- launch -----------------------------------------------------
extern "C" void kernel_launch(void* const* d_in, const int* in_sizes, int n_in,
                              void* d_out, int out_size) {
    const float* x = nullptr; const float* cat = nullptr; const float* phi = nullptr;
    const float* bias = nullptr; const int* y = nullptr;
    for (int i = 0; i < n_in; i++) {
        switch (in_sizes[i]) {
            case NB * ND: x    = (const float*)d_in[i]; break;
            case NN * ND: cat  = (const float*)d_in[i]; break;
            case NN:      y    = (const int*)d_in[i];   break;
            case NS * ND: phi  = (const float*)d_in[i]; break;
            case 1:       bias = (const float*)d_in[i]; break;
            default: break;
        }
    }
    float* out = (float*)d_out;

    cudaFuncSetAttribute(gemm_kernel, cudaFuncAttributeMaxDynamicSharedMemorySize, SM_TOTAL);

    const int tot4 = (NN * ND + NB * ND) / 4;
    convert_kernel<<<(tot4 + 255) / 256, 256>>>(cat, x);
    gemm_kernel<<<dim3(NB / BN, NN / BM), 256, SM_TOTAL>>>();
    theta_norm_kernel<<<528, 256>>>(x, phi);
    exp_pass<<<dim3(NB / 256, NN / 128), 256>>>(y);
    final_kernel<<<NB / 256, 256>>>(bias, out);
}

// round 13
// speedup vs baseline: 1.8660x; 1.1566x over previous
#include <cuda_runtime.h>
#include <cuda_fp16.h>
#include <cuda_fp8.h>
#include <cstdint>
#include <cstddef>

// Problem constants
#define NB 4096   // batch B
#define ND 768    // embedding D
#define NN 8192   // cat rows N
#define NS 4      // sources S

// ---------------- scratch (device globals; no allocations allowed) ----------
__device__ uint8_t g_cat8[NN * ND];                    // 6 MB (e4m3, x16 scale)
__device__ uint8_t g_x8[NB * ND];                      // 3 MB
__device__ __half g_conh[(size_t)NN * NB];             // 64 MB (fp16 con)
__device__ float g_s4part[128][NB];                    // norm4 partials
__device__ float g_inv_norm[NB];
__device__ float g_zpart[128][NB];                     // softmax denom partials
__device__ float g_wpart[128][NB];                     // y-weighted partials
__device__ float g_theta[NS][NB];

// ---------------- helpers ----------------------------------------------------
__device__ __forceinline__ uint32_t smem_u32(const void* p) {
    uint32_t a;
    asm("{ .reg .u64 t; cvta.to.shared.u64 t, %1; cvt.u32.u64 %0, t; }" : "=r"(a) : "l"(p));
    return a;
}

__device__ __forceinline__ void cp16(uint32_t smem, const void* gmem) {
    asm volatile("cp.async.cg.shared.global [%0], [%1], 16;\n" :: "r"(smem), "l"(gmem));
}

__device__ __forceinline__ void ldsm4(uint32_t* r, uint32_t addr) {
    asm volatile("ldmatrix.sync.aligned.m8n8.x4.shared.b16 {%0,%1,%2,%3}, [%4];"
                 : "=r"(r[0]), "=r"(r[1]), "=r"(r[2]), "=r"(r[3]) : "r"(addr));
}

// FP8 e4m3 MMA, m16n8k32, fp32 accumulate (legacy tensor path, 2x bf16 rate)
__device__ __forceinline__ void mma16832(float* c, const uint32_t* a, const uint32_t* b) {
    asm volatile(
        "mma.sync.aligned.m16n8k32.row.col.f32.e4m3.e4m3.f32 "
        "{%0,%1,%2,%3}, {%4,%5,%6,%7}, {%8,%9}, {%0,%1,%2,%3};\n"
        : "+f"(c[0]), "+f"(c[1]), "+f"(c[2]), "+f"(c[3])
        : "r"(a[0]), "r"(a[1]), "r"(a[2]), "r"(a[3]), "r"(b[0]), "r"(b[1]));
}

// ---------------- convert fp32 -> e4m3 (x16 scale) --------------------------
#define QSCALE 16.0f
#define DESCALE (1.0f / 256.0f)

__device__ __forceinline__ uint32_t pack_fp8x4(float4 v) {
    __nv_fp8x2_storage_t lo = __nv_cvt_float2_to_fp8x2(
        make_float2(v.x * QSCALE, v.y * QSCALE), __NV_SATFINITE, __NV_E4M3);
    __nv_fp8x2_storage_t hi = __nv_cvt_float2_to_fp8x2(
        make_float2(v.z * QSCALE, v.w * QSCALE), __NV_SATFINITE, __NV_E4M3);
    return (uint32_t)lo | ((uint32_t)hi << 16);
}

__global__ void convert_kernel(const float* __restrict__ cat,
                               const float* __restrict__ x) {
    int i = blockIdx.x * blockDim.x + threadIdx.x;
    const int totCat = NN * ND / 4;
    const int totX   = NB * ND / 4;
    if (i < totCat) {
        ((uint32_t*)g_cat8)[i] = pack_fp8x4(((const float4*)cat)[i]);
    } else if (i < totCat + totX) {
        int j = i - totCat;
        ((uint32_t*)g_x8)[j] = pack_fp8x4(((const float4*)x)[j]);
    }
}

// ---------------- GEMM: con[N,B] = cat[N,D] @ x[B,D]^T  (FP8) ---------------
// 128x128 CTA tile, 8 warps (2x4) at 64x32 each, K-chunk 64 fp8, 3-stage ring,
// 2 CTAs/SM.
#define BM 128
#define BN 128
#define BKB 64                  // fp8 elements (= bytes) per K chunk
#define NKC (ND / BKB)          // 12
#define ST 3
#define ASTRB 80                // bytes per smem row (64 + 16 pad) — CF for ldsm & cp
#define A_BYTES (BM * ASTRB)    // 10240
#define B_BYTES (BN * ASTRB)    // 10240
#define B_OFF (ST * A_BYTES)    // 30720
#define SM_TOTAL (ST * (A_BYTES + B_BYTES))            // 61440
#define CSTR 136                // epilogue staging stride (halves)

__device__ __forceinline__ void load_chunk(uint32_t sbase, int kt, int s,
                                           int bm0, int bn0, int tid) {
    const int k0 = kt * BKB;
    #pragma unroll
    for (int t = 0; t < 2; t++) {            // A: 128 rows x 4 x 16B
        int idx = tid + t * 256;
        int row = idx >> 2, c = (idx & 3) * 16;
        const void* g = g_cat8 + (size_t)(bm0 + row) * ND + k0 + c;
        cp16(sbase + s * A_BYTES + row * ASTRB + c, g);
    }
    #pragma unroll
    for (int t = 0; t < 2; t++) {            // B: 128 rows x 4 x 16B
        int idx = tid + t * 256;
        int row = idx >> 2, c = (idx & 3) * 16;
        const void* g = g_x8 + (size_t)(bn0 + row) * ND + k0 + c;
        cp16(sbase + B_OFF + s * B_BYTES + row * ASTRB + c, g);
    }
    asm volatile("cp.async.commit_group;\n" ::: "memory");
}

__global__ void __launch_bounds__(256, 2) gemm_kernel() {
    extern __shared__ char smem[];
    const uint32_t sbase = smem_u32(smem);

    const int tid  = threadIdx.x;
    const int lane = tid & 31;
    const int warp = tid >> 5;
    const int wm   = warp & 1;     // 2 warp rows (64 each)
    const int wn   = warp >> 1;    // 4 warp cols (32 each)
    const int bm0  = blockIdx.y * BM;    // n offset
    const int bn0  = blockIdx.x * BN;    // b offset

    const int lr = lane & 15;            // ldmatrix row within 16-row tile
    const int lh = (lane >> 4) * 16;     // 16-byte half select

    float acc[4][4][4];
    #pragma unroll
    for (int mt = 0; mt < 4; mt++)
        #pragma unroll
        for (int nt = 0; nt < 4; nt++)
            #pragma unroll
            for (int k = 0; k < 4; k++) acc[mt][nt][k] = 0.f;

    load_chunk(sbase, 0, 0, bm0, bn0, tid);
    load_chunk(sbase, 1, 1, bm0, bn0, tid);

    for (int kt = 0; kt < NKC; kt++) {
        const int s = kt % ST;
        if (kt < NKC - 1) asm volatile("cp.async.wait_group 1;\n" ::: "memory");
        else              asm volatile("cp.async.wait_group 0;\n" ::: "memory");
        __syncthreads();

        if (kt + 2 < NKC)
            load_chunk(sbase, kt + 2, (kt + 2) % ST, bm0, bn0, tid);

        #pragma unroll
        for (int ks = 0; ks < 2; ks++) {     // two k32 steps per 64-byte chunk
            uint32_t af[4][4], bb[2][4];
            const uint32_t abase =
                sbase + s * A_BYTES + (wm * 64 + lr) * ASTRB + ks * 32 + lh;
            #pragma unroll
            for (int mt = 0; mt < 4; mt++)
                ldsm4(af[mt], abase + mt * 16 * ASTRB);
            const uint32_t bbase =
                sbase + B_OFF + s * B_BYTES + (wn * 32 + lr) * ASTRB + ks * 32 + lh;
            #pragma unroll
            for (int p = 0; p < 2; p++)
                ldsm4(bb[p], bbase + p * 16 * ASTRB);

            #pragma unroll
            for (int mt = 0; mt < 4; mt++)
                #pragma unroll
                for (int nt = 0; nt < 4; nt++) {
                    uint32_t bfr[2] = { bb[nt >> 1][nt & 1], bb[nt >> 1][2 + (nt & 1)] };
                    mma16832(acc[mt][nt], af[mt], bfr);
                }
        }
    }

    // descale (inputs were x16 each)
    #pragma unroll
    for (int mt = 0; mt < 4; mt++)
        #pragma unroll
        for (int nt = 0; nt < 4; nt++)
            #pragma unroll
            for (int k = 0; k < 4; k++) acc[mt][nt][k] *= DESCALE;

    // ---- fused per-column sum(v^4) over this warp's 64 rows ----
    #pragma unroll
    for (int nt = 0; nt < 4; nt++) {
        float se = 0.f, so = 0.f;
        #pragma unroll
        for (int mt = 0; mt < 4; mt++) {
            float a0 = acc[mt][nt][0], a1 = acc[mt][nt][1];
            float a2 = acc[mt][nt][2], a3 = acc[mt][nt][3];
            se = fmaf(a0 * a0, a0 * a0, se); se = fmaf(a2 * a2, a2 * a2, se);
            so = fmaf(a1 * a1, a1 * a1, so); so = fmaf(a3 * a3, a3 * a3, so);
        }
        #pragma unroll
        for (int m = 4; m <= 16; m <<= 1) {   // reduce over lane>>2 (same lane&3)
            se += __shfl_xor_sync(0xffffffffu, se, m);
            so += __shfl_xor_sync(0xffffffffu, so, m);
        }
        if (lane < 4) {
            int c = bn0 + wn * 32 + nt * 8 + lane * 2;
            int slot = blockIdx.y * 2 + wm;
            g_s4part[slot][c]     = se;
            g_s4part[slot][c + 1] = so;
        }
    }

    // ---- epilogue: stage fp16 tile in smem, write coalesced rows ----
    __syncthreads();                       // smem ring no longer needed
    __half* sst = (__half*)smem;
    #pragma unroll
    for (int mt = 0; mt < 4; mt++) {
        #pragma unroll
        for (int nt = 0; nt < 4; nt++) {
            const int r = wm * 64 + mt * 16 + (lane >> 2);
            const int c = wn * 32 + nt * 8 + (lane & 3) * 2;
            *(__half2*)&sst[r * CSTR + c] =
                __floats2half2_rn(acc[mt][nt][0], acc[mt][nt][1]);
            *(__half2*)&sst[(r + 8) * CSTR + c] =
                __floats2half2_rn(acc[mt][nt][2], acc[mt][nt][3]);
        }
    }
    __syncthreads();
    #pragma unroll
    for (int i = 0; i < 16; i++) {
        const int r = warp * 16 + i;
        uint2 v = *(const uint2*)&sst[r * CSTR + lane * 4];
        *(uint2*)&g_conh[(size_t)(bm0 + r) * NB + bn0 + lane * 4] = v;
    }
}

// ---------------- theta + norm finalize (fused launch) ----------------------
__global__ void theta_norm_kernel(const float* __restrict__ x,
                                  const float* __restrict__ phi) {
    if (blockIdx.x >= 512) {
        int b = (blockIdx.x - 512) * 256 + threadIdx.x;
        float s = 0.f;
        #pragma unroll
        for (int i = 0; i < 128; i++) s += g_s4part[i][b];
        float nrm = sqrtf(sqrtf(s));
        nrm = fmaxf(nrm, 1e-12f);
        g_inv_norm[b] = 1.0f / nrm;
        return;
    }
    const int warp = threadIdx.x >> 5;
    const int lane = threadIdx.x & 31;
    const int b = blockIdx.x * 8 + warp;
    const float* xr = x + (size_t)b * ND;
    float xv[24];
    #pragma unroll
    for (int i = 0; i < 24; i++) xv[i] = xr[lane + i * 32];
    #pragma unroll
    for (int s = 0; s < NS; s++) {
        const float* pr = phi + (size_t)s * ND;
        float acc = 0.f;
        #pragma unroll
        for (int i = 0; i < 24; i++) acc = fmaf(xv[i], pr[lane + i * 32], acc);
        #pragma unroll
        for (int off = 16; off; off >>= 1) acc += __shfl_xor_sync(0xffffffffu, acc, off);
        if (lane == 0) g_theta[s][b] = expf(acc);
    }
}

// ---------------- pass B: per-column exp sums (Z, y-weighted) ---------------
// 4 columns per thread, 64 rows per block. grid (NB/1024, NN/64).
__global__ void exp_pass(const int* __restrict__ y) {
    const int b0 = blockIdx.x * 1024 + threadIdx.x * 4;
    const int n0 = blockIdx.y * 64;
    const float4 inv = *(const float4*)&g_inv_norm[b0];
    const __half* p = g_conh + (size_t)n0 * NB + b0;
    float z0 = 0.f, z1 = 0.f, z2 = 0.f, z3 = 0.f;
    float w0 = 0.f, w1 = 0.f, w2 = 0.f, w3 = 0.f;
    #pragma unroll 4
    for (int i = 0; i < 64; i++) {
        uint2 v = *(const uint2*)(p + (size_t)i * NB);
        __half2 h01 = *reinterpret_cast<__half2*>(&v.x);
        __half2 h23 = *reinterpret_cast<__half2*>(&v.y);
        float2 f01 = __half22float2(h01);
        float2 f23 = __half22float2(h23);
        float m = (float)__ldg(&y[n0 + i]);
        float e0 = __expf(f01.x * inv.x);
        float e1 = __expf(f01.y * inv.y);
        float e2 = __expf(f23.x * inv.z);
        float e3 = __expf(f23.y * inv.w);
        z0 += e0; z1 += e1; z2 += e2; z3 += e3;
        w0 = fmaf(m, e0, w0); w1 = fmaf(m, e1, w1);
        w2 = fmaf(m, e2, w2); w3 = fmaf(m, e3, w3);
    }
    *(float4*)&g_zpart[blockIdx.y][b0] = make_float4(z0, z1, z2, z3);
    *(float4*)&g_wpart[blockIdx.y][b0] = make_float4(w0, w1, w2, w3);
}

// ---------------- final: sigmoid( sum_s theta*wsum / Z + bias ) -------------
__global__ void final_kernel(const float* __restrict__ bias, float* __restrict__ out) {
    int b = blockIdx.x * 256 + threadIdx.x;
    float Z = 0.f;
    #pragma unroll
    for (int i = 0; i < 128; i++) Z += g_zpart[i][b];
    float sum = 0.f;
    #pragma unroll
    for (int s = 0; s < NS; s++) {
        float w = 0.f;
        #pragma unroll
        for (int i = 0; i < 32; i++) w += g_wpart[s * 32 + i][b];
        sum += w * g_theta[s][b];
    }
    float r = sum / Z + bias[0];
    out[b] = 1.0f / (1.0f + expf(-r));
}

// ---------------- launch -----------------------------------------------------
extern "C" void kernel_launch(void* const* d_in, const int* in_sizes, int n_in,
                              void* d_out, int out_size) {
    const float* x = nullptr; const float* cat = nullptr; const float* phi = nullptr;
    const float* bias = nullptr; const int* y = nullptr;
    for (int i = 0; i < n_in; i++) {
        switch (in_sizes[i]) {
            case NB * ND: x    = (const float*)d_in[i]; break;
            case NN * ND: cat  = (const float*)d_in[i]; break;
            case NN:      y    = (const int*)d_in[i];   break;
            case NS * ND: phi  = (const float*)d_in[i]; break;
            case 1:       bias = (const float*)d_in[i]; break;
            default: break;
        }
    }
    float* out = (float*)d_out;

    cudaFuncSetAttribute(gemm_kernel, cudaFuncAttributeMaxDynamicSharedMemorySize, SM_TOTAL);

    const int tot4 = (NN * ND + NB * ND) / 4;
    convert_kernel<<<(tot4 + 255) / 256, 256>>>(cat, x);
    gemm_kernel<<<dim3(NB / BN, NN / BM), 256, SM_TOTAL>>>();
    theta_norm_kernel<<<528, 256>>>(x, phi);
    exp_pass<<<dim3(NB / 1024, NN / 64), 256>>>(y);
    final_kernel<<<NB / 256, 256>>>(bias, out);
}